// round 6
// baseline (speedup 1.0000x reference)
#include <cuda_runtime.h>
#include <cuda_bf16.h>

#define N_NODES 50000
#define E_EDGES 1600000
#define DIM     128

// ---------------------------------------------------------------------------
// Scratch (device globals — no allocation allowed)
// ---------------------------------------------------------------------------
__device__ float g_h   [N_NODES * DIM];   // h = x @ W
__device__ float g_x1  [N_NODES * DIM];   // layer-1 output
__device__ float g_dinv[N_NODES];
__device__ int   g_deg [N_NODES];
__device__ int   g_off [N_NODES + 1];     // CSR row offsets (by dst)
__device__ int   g_cur [N_NODES];         // insertion cursors
__device__ int2  g_edge[E_EDGES];         // {src, __float_as_int(norm)} sorted by dst

// ---------------------------------------------------------------------------
// Degree histogram
// ---------------------------------------------------------------------------
__global__ void zero_deg_kernel() {
    int i = blockIdx.x * blockDim.x + threadIdx.x;
    if (i < N_NODES) g_deg[i] = 0;
}

__global__ void hist_kernel(const int* __restrict__ dst) {
    int e = blockIdx.x * blockDim.x + threadIdx.x;
    if (e < E_EDGES) atomicAdd(&g_deg[dst[e]], 1);
}

// ---------------------------------------------------------------------------
// Single-block scan: exclusive prefix of deg -> g_off, g_cur; dinv = rsqrt(deg+1)
// ---------------------------------------------------------------------------
__global__ __launch_bounds__(1024) void scan_kernel() {
    __shared__ int sp[1024];
    const int T = 1024;
    const int tid = threadIdx.x;
    const int chunk = (N_NODES + T - 1) / T;     // 49
    const int lo = tid * chunk;
    const int hi = min(lo + chunk, N_NODES);

    int s = 0;
    for (int i = lo; i < hi; i++) s += g_deg[i];
    sp[tid] = s;
    __syncthreads();

    // Hillis-Steele inclusive scan
    for (int off = 1; off < T; off <<= 1) {
        int v = (tid >= off) ? sp[tid - off] : 0;
        __syncthreads();
        sp[tid] += v;
        __syncthreads();
    }

    int base = (tid > 0) ? sp[tid - 1] : 0;      // exclusive prefix
    for (int i = lo; i < hi; i++) {
        g_off[i] = base;
        g_cur[i] = base;
        g_dinv[i] = rsqrtf((float)(g_deg[i] + 1));   // +1 for self-loop
        base += g_deg[i];
    }
    if (tid == 0) g_off[N_NODES] = E_EDGES;
}

// ---------------------------------------------------------------------------
// Reorder edges into dst-sorted CSR; store {src, norm} packed
// ---------------------------------------------------------------------------
__global__ void reorder_kernel(const int* __restrict__ src, const int* __restrict__ dst) {
    int e = blockIdx.x * blockDim.x + threadIdx.x;
    if (e < E_EDGES) {
        int d = dst[e];
        int s = src[e];
        int p = atomicAdd(&g_cur[d], 1);
        float nm = g_dinv[d] * g_dinv[s];
        g_edge[p] = make_int2(s, __float_as_int(nm));
    }
}

// ---------------------------------------------------------------------------
// GEMM: C[n,128] = A[n,128] @ W[128,128]  using packed fma.rn.f32x2 (2 FMA/op)
// Block 256 threads, tile 128x128, K-chunks of 32. Thread: 8 rows (4 pairs) x 8 cols.
// ---------------------------------------------------------------------------
#define BM 128
#define BN 128
#define BK 32
#define BMP (BM + 4)   // padded row to kill smem store bank conflicts

typedef unsigned long long ull;

__device__ __forceinline__ void ffma2(ull& d, ull a, ull b) {
    asm("fma.rn.f32x2 %0, %1, %2, %0;" : "+l"(d) : "l"(a), "l"(b));
}

__global__ __launch_bounds__(256) void gemm_kernel(
    const float* __restrict__ A, const float* __restrict__ W,
    float* __restrict__ C, int n)
{
    __shared__ float xsf[BK][BMP];        // [k][m]  (pairs of rows read as 8B)
    __shared__ float2 ws2[BK][BN];        // {w, w} duplicated

    const int tid  = threadIdx.x;
    const int c0   = tid & 15;            // col base; cols = c0 + j*16
    const int mp   = (tid >> 4) * 4;      // row-pair base (4 pairs = 8 rows)
    const int row0 = blockIdx.x * BM;

    ull acc[4][8];
    #pragma unroll
    for (int p = 0; p < 4; p++)
        #pragma unroll
        for (int j = 0; j < 8; j++) acc[p][j] = 0ull;

    for (int kc = 0; kc < DIM; kc += BK) {
        // A tile: 128x32, 16 floats/thread, coalesced over k
        #pragma unroll
        for (int i = 0; i < 16; i++) {
            int t = tid + i * 256;
            int k = t & 31, m = t >> 5;
            int row = row0 + m;
            xsf[k][m] = (row < n) ? A[(size_t)row * DIM + kc + k] : 0.f;
        }
        // W tile duplicated: 32x128 values, 16/thread, coalesced over col
        #pragma unroll
        for (int i = 0; i < 16; i++) {
            int t = tid + i * 256;
            int k = t >> 7, col = t & 127;
            float w = W[(size_t)(kc + k) * DIM + col];
            ws2[k][col] = make_float2(w, w);
        }
        __syncthreads();

        #pragma unroll
        for (int kk = 0; kk < BK; kk++) {
            ull a[4];
            #pragma unroll
            for (int p = 0; p < 4; p++)
                a[p] = *reinterpret_cast<const ull*>(&xsf[kk][(mp + p) * 2]);
            ull w[8];
            #pragma unroll
            for (int j = 0; j < 8; j++)
                w[j] = *reinterpret_cast<const ull*>(&ws2[kk][c0 + j * 16]);
            #pragma unroll
            for (int p = 0; p < 4; p++)
                #pragma unroll
                for (int j = 0; j < 8; j++)
                    ffma2(acc[p][j], a[p], w[j]);
        }
        __syncthreads();
    }

    #pragma unroll
    for (int p = 0; p < 4; p++) {
        int r0 = row0 + (mp + p) * 2;
        if (r0 < n) {
            #pragma unroll
            for (int j = 0; j < 8; j++)
                C[(size_t)r0 * DIM + c0 + j * 16] =
                    __uint_as_float((unsigned)(acc[p][j] & 0xffffffffull));
        }
        if (r0 + 1 < n) {
            #pragma unroll
            for (int j = 0; j < 8; j++)
                C[(size_t)(r0 + 1) * DIM + c0 + j * 16] =
                    __uint_as_float((unsigned)(acc[p][j] >> 32));
        }
    }
}

// ---------------------------------------------------------------------------
// Fused aggregate: warp per node.
// out[d] = relu( h[d]*dinv[d]^2 + sum_e h[src_e]*norm_e + b )
// Edge list is dst-sorted CSR -> sequential coalesced edge reads, no atomics,
// single coalesced output write.
// ---------------------------------------------------------------------------
__global__ __launch_bounds__(256) void aggregate_kernel(
    const float* __restrict__ h, const float* __restrict__ b,
    float* __restrict__ out)
{
    const int lane = threadIdx.x & 31;
    const int node = (blockIdx.x * blockDim.x + threadIdx.x) >> 5;  // exact: 6250*8 = 50000
    if (node >= N_NODES) return;

    const int beg = g_off[node];
    const int end = g_off[node + 1];
    const float dv = g_dinv[node];
    const float sc = dv * dv;

    float4 acc = *(const float4*)(h + (size_t)node * DIM + lane * 4);
    acc.x *= sc; acc.y *= sc; acc.z *= sc; acc.w *= sc;

    int e = beg;
    for (; e + 2 <= end; e += 2) {
        int2 e0 = g_edge[e];
        int2 e1 = g_edge[e + 1];
        float n0 = __int_as_float(e0.y);
        float n1 = __int_as_float(e1.y);
        float4 v0 = *(const float4*)(h + (size_t)e0.x * DIM + lane * 4);
        float4 v1 = *(const float4*)(h + (size_t)e1.x * DIM + lane * 4);
        acc.x += v0.x * n0; acc.y += v0.y * n0; acc.z += v0.z * n0; acc.w += v0.w * n0;
        acc.x += v1.x * n1; acc.y += v1.y * n1; acc.z += v1.z * n1; acc.w += v1.w * n1;
    }
    if (e < end) {
        int2 e0 = g_edge[e];
        float n0 = __int_as_float(e0.y);
        float4 v0 = *(const float4*)(h + (size_t)e0.x * DIM + lane * 4);
        acc.x += v0.x * n0; acc.y += v0.y * n0; acc.z += v0.z * n0; acc.w += v0.w * n0;
    }

    float4 b4 = *(const float4*)(b + lane * 4);
    acc.x = fmaxf(acc.x + b4.x, 0.f);
    acc.y = fmaxf(acc.y + b4.y, 0.f);
    acc.z = fmaxf(acc.z + b4.z, 0.f);
    acc.w = fmaxf(acc.w + b4.w, 0.f);
    *(float4*)(out + (size_t)node * DIM + lane * 4) = acc;
}

// ---------------------------------------------------------------------------
// Launch
// ---------------------------------------------------------------------------
extern "C" void kernel_launch(void* const* d_in, const int* in_sizes, int n_in,
                              void* d_out, int out_size)
{
    const float* x   = (const float*)d_in[0];
    const int*   ei  = (const int*)  d_in[1];
    const float* W0  = (const float*)d_in[2];
    const float* b0  = (const float*)d_in[3];
    const float* W1  = (const float*)d_in[4];
    const float* b1  = (const float*)d_in[5];
    float*       out = (float*)d_out;

    const int* src = ei;
    const int* dst = ei + E_EDGES;

    float *h_ptr, *x1_ptr;
    cudaGetSymbolAddress((void**)&h_ptr,  g_h);
    cudaGetSymbolAddress((void**)&x1_ptr, g_x1);

    const int TB = 256;
    const int gridN = (N_NODES + TB - 1) / TB;
    const int gridE = (E_EDGES + TB - 1) / TB;
    const int gridG = (N_NODES + BM - 1) / BM;
    const int gridA = (N_NODES * 32 + TB - 1) / TB;   // warp per node

    // CSR + normalization precompute (once, reused by both layers)
    zero_deg_kernel<<<gridN, TB>>>();
    hist_kernel<<<gridE, TB>>>(dst);
    scan_kernel<<<1, 1024>>>();
    reorder_kernel<<<gridE, TB>>>(src, dst);

    // layer 1
    gemm_kernel<<<gridG, TB>>>(x, W0, h_ptr, N_NODES);
    aggregate_kernel<<<gridA, TB>>>(h_ptr, b0, x1_ptr);

    // layer 2
    gemm_kernel<<<gridG, TB>>>(x1_ptr, W1, h_ptr, N_NODES);
    aggregate_kernel<<<gridA, TB>>>(h_ptr, b1, out);
}

// round 7
// speedup vs baseline: 1.0033x; 1.0033x over previous
#include <cuda_runtime.h>
#include <cuda_bf16.h>

#define N_NODES 50000
#define E_EDGES 1600000
#define DIM     128

// ---------------------------------------------------------------------------
// Scratch (device globals — no allocation allowed)
// ---------------------------------------------------------------------------
__device__ float g_h   [N_NODES * DIM];   // h = x @ W
__device__ float g_x1  [N_NODES * DIM];   // layer-1 output
__device__ float g_dinv[N_NODES];
__device__ int   g_deg [N_NODES];
__device__ int   g_off [N_NODES + 1];     // CSR row offsets (by dst)
__device__ int   g_cur [N_NODES];         // insertion cursors
__device__ int2  g_edge[E_EDGES];         // {src, __float_as_int(norm)} sorted by dst

// ---------------------------------------------------------------------------
// Degree histogram
// ---------------------------------------------------------------------------
__global__ void zero_deg_kernel() {
    int i = blockIdx.x * blockDim.x + threadIdx.x;
    if (i < N_NODES) g_deg[i] = 0;
}

__global__ void hist_kernel(const int* __restrict__ dst) {
    int e = blockIdx.x * blockDim.x + threadIdx.x;
    if (e < E_EDGES) atomicAdd(&g_deg[dst[e]], 1);
}

// ---------------------------------------------------------------------------
// Single-block scan: exclusive prefix of deg -> g_off, g_cur; dinv = rsqrt(deg+1)
// ---------------------------------------------------------------------------
__global__ __launch_bounds__(1024) void scan_kernel() {
    __shared__ int sp[1024];
    const int T = 1024;
    const int tid = threadIdx.x;
    const int chunk = (N_NODES + T - 1) / T;     // 49
    const int lo = tid * chunk;
    const int hi = min(lo + chunk, N_NODES);

    int s = 0;
    for (int i = lo; i < hi; i++) s += g_deg[i];
    sp[tid] = s;
    __syncthreads();

    // Hillis-Steele inclusive scan
    for (int off = 1; off < T; off <<= 1) {
        int v = (tid >= off) ? sp[tid - off] : 0;
        __syncthreads();
        sp[tid] += v;
        __syncthreads();
    }

    int base = (tid > 0) ? sp[tid - 1] : 0;      // exclusive prefix
    for (int i = lo; i < hi; i++) {
        g_off[i] = base;
        g_cur[i] = base;
        g_dinv[i] = rsqrtf((float)(g_deg[i] + 1));   // +1 for self-loop
        base += g_deg[i];
    }
    if (tid == 0) g_off[N_NODES] = E_EDGES;
}

// ---------------------------------------------------------------------------
// Reorder edges into dst-sorted CSR; store {src, norm} packed
// ---------------------------------------------------------------------------
__global__ void reorder_kernel(const int* __restrict__ src, const int* __restrict__ dst) {
    int e = blockIdx.x * blockDim.x + threadIdx.x;
    if (e < E_EDGES) {
        int d = dst[e];
        int s = src[e];
        int p = atomicAdd(&g_cur[d], 1);
        float nm = g_dinv[d] * g_dinv[s];
        g_edge[p] = make_int2(s, __float_as_int(nm));
    }
}

// ---------------------------------------------------------------------------
// GEMM: C[n,128] = A[n,128] @ W[128,128]  using packed fma.rn.f32x2 (2 FMA/op)
// Block 256 threads, tile 128x128, K-chunks of 32. Thread: 8 rows (4 pairs) x 8 cols.
// ---------------------------------------------------------------------------
#define BM 128
#define BN 128
#define BK 32
#define BMP (BM + 4)   // padded row to kill smem store bank conflicts

typedef unsigned long long ull;

__device__ __forceinline__ void ffma2(ull& d, ull a, ull b) {
    asm("fma.rn.f32x2 %0, %1, %2, %0;" : "+l"(d) : "l"(a), "l"(b));
}

__global__ __launch_bounds__(256) void gemm_kernel(
    const float* __restrict__ A, const float* __restrict__ W,
    float* __restrict__ C, int n)
{
    __shared__ float xsf[BK][BMP];        // [k][m]  (pairs of rows read as 8B)
    __shared__ float2 ws2[BK][BN];        // {w, w} duplicated

    const int tid  = threadIdx.x;
    const int c0   = tid & 15;            // col base; cols = c0 + j*16
    const int mp   = (tid >> 4) * 4;      // row-pair base (4 pairs = 8 rows)
    const int row0 = blockIdx.x * BM;

    ull acc[4][8];
    #pragma unroll
    for (int p = 0; p < 4; p++)
        #pragma unroll
        for (int j = 0; j < 8; j++) acc[p][j] = 0ull;

    for (int kc = 0; kc < DIM; kc += BK) {
        // A tile: 128x32, 16 floats/thread, coalesced over k
        #pragma unroll
        for (int i = 0; i < 16; i++) {
            int t = tid + i * 256;
            int k = t & 31, m = t >> 5;
            int row = row0 + m;
            xsf[k][m] = (row < n) ? A[(size_t)row * DIM + kc + k] : 0.f;
        }
        // W tile duplicated: 32x128 values, 16/thread, coalesced over col
        #pragma unroll
        for (int i = 0; i < 16; i++) {
            int t = tid + i * 256;
            int k = t >> 7, col = t & 127;
            float w = W[(size_t)(kc + k) * DIM + col];
            ws2[k][col] = make_float2(w, w);
        }
        __syncthreads();

        #pragma unroll
        for (int kk = 0; kk < BK; kk++) {
            ull a[4];
            #pragma unroll
            for (int p = 0; p < 4; p++)
                a[p] = *reinterpret_cast<const ull*>(&xsf[kk][(mp + p) * 2]);
            ull w[8];
            #pragma unroll
            for (int j = 0; j < 8; j++)
                w[j] = *reinterpret_cast<const ull*>(&ws2[kk][c0 + j * 16]);
            #pragma unroll
            for (int p = 0; p < 4; p++)
                #pragma unroll
                for (int j = 0; j < 8; j++)
                    ffma2(acc[p][j], a[p], w[j]);
        }
        __syncthreads();
    }

    #pragma unroll
    for (int p = 0; p < 4; p++) {
        int r0 = row0 + (mp + p) * 2;
        if (r0 < n) {
            #pragma unroll
            for (int j = 0; j < 8; j++)
                C[(size_t)r0 * DIM + c0 + j * 16] =
                    __uint_as_float((unsigned)(acc[p][j] & 0xffffffffull));
        }
        if (r0 + 1 < n) {
            #pragma unroll
            for (int j = 0; j < 8; j++)
                C[(size_t)(r0 + 1) * DIM + c0 + j * 16] =
                    __uint_as_float((unsigned)(acc[p][j] >> 32));
        }
    }
}

// ---------------------------------------------------------------------------
// Fused aggregate: warp per node.
// out[d] = relu( h[d]*dinv[d]^2 + sum_e h[src_e]*norm_e + b )
// Edge list is dst-sorted CSR -> sequential coalesced edge reads, no atomics,
// single coalesced output write.
// ---------------------------------------------------------------------------
__global__ __launch_bounds__(256) void aggregate_kernel(
    const float* __restrict__ h, const float* __restrict__ b,
    float* __restrict__ out)
{
    const int lane = threadIdx.x & 31;
    const int node = (blockIdx.x * blockDim.x + threadIdx.x) >> 5;  // exact: 6250*8 = 50000
    if (node >= N_NODES) return;

    const int beg = g_off[node];
    const int end = g_off[node + 1];
    const float dv = g_dinv[node];
    const float sc = dv * dv;

    float4 acc = *(const float4*)(h + (size_t)node * DIM + lane * 4);
    acc.x *= sc; acc.y *= sc; acc.z *= sc; acc.w *= sc;

    int e = beg;
    for (; e + 2 <= end; e += 2) {
        int2 e0 = g_edge[e];
        int2 e1 = g_edge[e + 1];
        float n0 = __int_as_float(e0.y);
        float n1 = __int_as_float(e1.y);
        float4 v0 = *(const float4*)(h + (size_t)e0.x * DIM + lane * 4);
        float4 v1 = *(const float4*)(h + (size_t)e1.x * DIM + lane * 4);
        acc.x += v0.x * n0; acc.y += v0.y * n0; acc.z += v0.z * n0; acc.w += v0.w * n0;
        acc.x += v1.x * n1; acc.y += v1.y * n1; acc.z += v1.z * n1; acc.w += v1.w * n1;
    }
    if (e < end) {
        int2 e0 = g_edge[e];
        float n0 = __int_as_float(e0.y);
        float4 v0 = *(const float4*)(h + (size_t)e0.x * DIM + lane * 4);
        acc.x += v0.x * n0; acc.y += v0.y * n0; acc.z += v0.z * n0; acc.w += v0.w * n0;
    }

    float4 b4 = *(const float4*)(b + lane * 4);
    acc.x = fmaxf(acc.x + b4.x, 0.f);
    acc.y = fmaxf(acc.y + b4.y, 0.f);
    acc.z = fmaxf(acc.z + b4.z, 0.f);
    acc.w = fmaxf(acc.w + b4.w, 0.f);
    *(float4*)(out + (size_t)node * DIM + lane * 4) = acc;
}

// ---------------------------------------------------------------------------
// Launch
// ---------------------------------------------------------------------------
extern "C" void kernel_launch(void* const* d_in, const int* in_sizes, int n_in,
                              void* d_out, int out_size)
{
    const float* x   = (const float*)d_in[0];
    const int*   ei  = (const int*)  d_in[1];
    const float* W0  = (const float*)d_in[2];
    const float* b0  = (const float*)d_in[3];
    const float* W1  = (const float*)d_in[4];
    const float* b1  = (const float*)d_in[5];
    float*       out = (float*)d_out;

    const int* src = ei;
    const int* dst = ei + E_EDGES;

    float *h_ptr, *x1_ptr;
    cudaGetSymbolAddress((void**)&h_ptr,  g_h);
    cudaGetSymbolAddress((void**)&x1_ptr, g_x1);

    const int TB = 256;
    const int gridN = (N_NODES + TB - 1) / TB;
    const int gridE = (E_EDGES + TB - 1) / TB;
    const int gridG = (N_NODES + BM - 1) / BM;
    const int gridA = (N_NODES * 32 + TB - 1) / TB;   // warp per node

    // CSR + normalization precompute (once, reused by both layers)
    zero_deg_kernel<<<gridN, TB>>>();
    hist_kernel<<<gridE, TB>>>(dst);
    scan_kernel<<<1, 1024>>>();
    reorder_kernel<<<gridE, TB>>>(src, dst);

    // layer 1
    gemm_kernel<<<gridG, TB>>>(x, W0, h_ptr, N_NODES);
    aggregate_kernel<<<gridA, TB>>>(h_ptr, b0, x1_ptr);

    // layer 2
    gemm_kernel<<<gridG, TB>>>(x1_ptr, W1, h_ptr, N_NODES);
    aggregate_kernel<<<gridA, TB>>>(h_ptr, b1, out);
}

// round 8
// speedup vs baseline: 1.1450x; 1.1412x over previous
#include <cuda_runtime.h>
#include <cuda_bf16.h>

#define N_NODES 50000
#define E_EDGES 1600000
#define DIM     128

// ---------------------------------------------------------------------------
// Scratch (device globals — no allocation allowed)
// ---------------------------------------------------------------------------
__device__ float g_h   [N_NODES * DIM];   // h = x @ W
__device__ float g_x1  [N_NODES * DIM];   // layer-1 output
__device__ float g_dinv[N_NODES];
__device__ int   g_deg [N_NODES];
__device__ int   g_off [N_NODES + 1];     // CSR row offsets (by dst)
__device__ int   g_cur [N_NODES];         // insertion cursors
__device__ int2  g_edge[E_EDGES];         // {src, __float_as_int(norm)} sorted by dst

// Pre-split weights, transposed to n-major: Wt[n][k], bf16 hi/lo
__device__ __nv_bfloat16 g_wt_hi[2][DIM * DIM];
__device__ __nv_bfloat16 g_wt_lo[2][DIM * DIM];

// ---------------------------------------------------------------------------
// Degree histogram (ILP-4)
// ---------------------------------------------------------------------------
__global__ void zero_deg_kernel() {
    int i = blockIdx.x * blockDim.x + threadIdx.x;
    if (i < N_NODES) g_deg[i] = 0;
}

__global__ void hist_kernel(const int* __restrict__ dst) {
    int base = (blockIdx.x * blockDim.x + threadIdx.x) * 4;
    if (base < E_EDGES) {   // E divisible by 4
        int4 d4 = *(const int4*)(dst + base);
        atomicAdd(&g_deg[d4.x], 1);
        atomicAdd(&g_deg[d4.y], 1);
        atomicAdd(&g_deg[d4.z], 1);
        atomicAdd(&g_deg[d4.w], 1);
    }
}

// ---------------------------------------------------------------------------
// Single-block scan: exclusive prefix of deg -> g_off, g_cur; dinv = rsqrt(deg+1)
// ---------------------------------------------------------------------------
__global__ __launch_bounds__(1024) void scan_kernel() {
    __shared__ int sp[1024];
    const int T = 1024;
    const int tid = threadIdx.x;
    const int chunk = (N_NODES + T - 1) / T;
    const int lo = tid * chunk;
    const int hi = min(lo + chunk, N_NODES);

    int s = 0;
    for (int i = lo; i < hi; i++) s += g_deg[i];
    sp[tid] = s;
    __syncthreads();

    for (int off = 1; off < T; off <<= 1) {
        int v = (tid >= off) ? sp[tid - off] : 0;
        __syncthreads();
        sp[tid] += v;
        __syncthreads();
    }

    int base = (tid > 0) ? sp[tid - 1] : 0;
    for (int i = lo; i < hi; i++) {
        g_off[i] = base;
        g_cur[i] = base;
        g_dinv[i] = rsqrtf((float)(g_deg[i] + 1));
        base += g_deg[i];
    }
    if (tid == 0) g_off[N_NODES] = E_EDGES;
}

// ---------------------------------------------------------------------------
// Reorder edges into dst-sorted CSR (ILP-4)
// ---------------------------------------------------------------------------
__global__ void reorder_kernel(const int* __restrict__ src, const int* __restrict__ dst) {
    int base = (blockIdx.x * blockDim.x + threadIdx.x) * 4;
    if (base < E_EDGES) {   // E divisible by 4
        int4 d4 = *(const int4*)(dst + base);
        int4 s4 = *(const int4*)(src + base);
        int p0 = atomicAdd(&g_cur[d4.x], 1);
        int p1 = atomicAdd(&g_cur[d4.y], 1);
        int p2 = atomicAdd(&g_cur[d4.z], 1);
        int p3 = atomicAdd(&g_cur[d4.w], 1);
        float n0 = g_dinv[d4.x] * g_dinv[s4.x];
        float n1 = g_dinv[d4.y] * g_dinv[s4.y];
        float n2 = g_dinv[d4.z] * g_dinv[s4.z];
        float n3 = g_dinv[d4.w] * g_dinv[s4.w];
        g_edge[p0] = make_int2(s4.x, __float_as_int(n0));
        g_edge[p1] = make_int2(s4.y, __float_as_int(n1));
        g_edge[p2] = make_int2(s4.z, __float_as_int(n2));
        g_edge[p3] = make_int2(s4.w, __float_as_int(n3));
    }
}

// ---------------------------------------------------------------------------
// Weight prep: split W (k-major [k][n]) into bf16 hi/lo, transposed to [n][k]
// ---------------------------------------------------------------------------
__global__ void wsplit_kernel(const float* __restrict__ W,
                              __nv_bfloat16* __restrict__ hi,
                              __nv_bfloat16* __restrict__ lo) {
    int idx = blockIdx.x * blockDim.x + threadIdx.x;   // 16384
    if (idx < DIM * DIM) {
        int k = idx >> 7, n = idx & 127;
        float v = W[idx];
        __nv_bfloat16 h = __float2bfloat16(v);
        __nv_bfloat16 l = __float2bfloat16(v - __bfloat162float(h));
        hi[n * DIM + k] = h;
        lo[n * DIM + k] = l;
    }
}

// ---------------------------------------------------------------------------
// Tensor-core GEMM: C[n,128] = A[n,128] @ W[128,128] in split-bf16
//   (hi+lo decomposition: keep hi*hi + hi*lo + lo*hi; error ~2^-17)
// Block 256 threads (8 warps, 4x2), tile 128x128, K-chunks of 32.
// Warp computes 32x64 via mma.sync.m16n8k16 (2 m-tiles x 8 n-tiles x 3 combos).
// ---------------------------------------------------------------------------
#define GBM  128
#define GBK  32
#define GPAD 40    // row stride in bf16 -> conflict-free fragment LDS

__device__ __forceinline__ void mma16816(float* c, const unsigned* a, const unsigned* b) {
    asm volatile(
        "mma.sync.aligned.m16n8k16.row.col.f32.bf16.bf16.f32 "
        "{%0,%1,%2,%3}, {%4,%5,%6,%7}, {%8,%9}, {%0,%1,%2,%3};"
        : "+f"(c[0]), "+f"(c[1]), "+f"(c[2]), "+f"(c[3])
        : "r"(a[0]), "r"(a[1]), "r"(a[2]), "r"(a[3]), "r"(b[0]), "r"(b[1]));
}

__global__ __launch_bounds__(256) void gemm_tc_kernel(
    const float* __restrict__ A,
    const __nv_bfloat16* __restrict__ Wt_hi,
    const __nv_bfloat16* __restrict__ Wt_lo,
    float* __restrict__ C, int n)
{
    __shared__ __nv_bfloat16 sAh[GBM][GPAD];
    __shared__ __nv_bfloat16 sAl[GBM][GPAD];
    __shared__ __nv_bfloat16 sWh[DIM][GPAD];
    __shared__ __nv_bfloat16 sWl[DIM][GPAD];

    const int tid   = threadIdx.x;
    const int lane  = tid & 31;
    const int w     = tid >> 5;
    const int wm    = w & 3;          // row block (32 rows)
    const int wn    = w >> 2;         // col block (64 cols)
    const int gq    = lane >> 2;      // 0..7
    const int gp    = lane & 3;       // 0..3
    const int row0  = blockIdx.x * GBM;

    float c[2][8][4];
    #pragma unroll
    for (int im = 0; im < 2; im++)
        #pragma unroll
        for (int j = 0; j < 8; j++)
            #pragma unroll
            for (int q = 0; q < 4; q++) c[im][j][q] = 0.f;

    for (int kc = 0; kc < DIM; kc += GBK) {
        // --- A tile: 128x32 f32 -> split bf16 hi/lo. 2048 float2, 8/thread ---
        #pragma unroll
        for (int i = 0; i < 8; i++) {
            int idx = tid + i * 256;
            int m   = idx >> 4;
            int k2  = (idx & 15) * 2;
            int row = row0 + m;
            float2 v = (row < n) ? *(const float2*)(A + (size_t)row * DIM + kc + k2)
                                 : make_float2(0.f, 0.f);
            __nv_bfloat16 hx = __float2bfloat16(v.x);
            __nv_bfloat16 hy = __float2bfloat16(v.y);
            __nv_bfloat16 lx = __float2bfloat16(v.x - __bfloat162float(hx));
            __nv_bfloat16 ly = __float2bfloat16(v.y - __bfloat162float(hy));
            __nv_bfloat162 ph; ph.x = hx; ph.y = hy;
            __nv_bfloat162 pl; pl.x = lx; pl.y = ly;
            *(__nv_bfloat162*)&sAh[m][k2] = ph;
            *(__nv_bfloat162*)&sAl[m][k2] = pl;
        }
        // --- W tile: pre-split n-major global -> smem. 2048 u32, 8/thread ---
        #pragma unroll
        for (int i = 0; i < 8; i++) {
            int idx = tid + i * 256;
            int nn  = idx >> 4;
            int kp  = (idx & 15) * 2;
            *(unsigned*)&sWh[nn][kp] = *(const unsigned*)(Wt_hi + nn * DIM + kc + kp);
            *(unsigned*)&sWl[nn][kp] = *(const unsigned*)(Wt_lo + nn * DIM + kc + kp);
        }
        __syncthreads();

        #pragma unroll
        for (int ks = 0; ks < 2; ks++) {
            const int kb = ks * 16;
            // B fragments: b0=(k0..k0+1, n), b1=(k0+8..k0+9, n); n = gq
            unsigned bh[8][2], bl[8][2];
            #pragma unroll
            for (int j = 0; j < 8; j++) {
                int nn = wn * 64 + j * 8 + gq;
                bh[j][0] = *(const unsigned*)&sWh[nn][kb + gp * 2];
                bh[j][1] = *(const unsigned*)&sWh[nn][kb + gp * 2 + 8];
                bl[j][0] = *(const unsigned*)&sWl[nn][kb + gp * 2];
                bl[j][1] = *(const unsigned*)&sWl[nn][kb + gp * 2 + 8];
            }
            #pragma unroll
            for (int im = 0; im < 2; im++) {
                int mr = wm * 32 + im * 16 + gq;
                unsigned ah[4], al[4];
                ah[0] = *(const unsigned*)&sAh[mr    ][kb + gp * 2];
                ah[1] = *(const unsigned*)&sAh[mr + 8][kb + gp * 2];
                ah[2] = *(const unsigned*)&sAh[mr    ][kb + gp * 2 + 8];
                ah[3] = *(const unsigned*)&sAh[mr + 8][kb + gp * 2 + 8];
                al[0] = *(const unsigned*)&sAl[mr    ][kb + gp * 2];
                al[1] = *(const unsigned*)&sAl[mr + 8][kb + gp * 2];
                al[2] = *(const unsigned*)&sAl[mr    ][kb + gp * 2 + 8];
                al[3] = *(const unsigned*)&sAl[mr + 8][kb + gp * 2 + 8];
                #pragma unroll
                for (int j = 0; j < 8; j++) {
                    mma16816(c[im][j], ah, bh[j]);   // hi*hi
                    mma16816(c[im][j], ah, bl[j]);   // hi*lo
                    mma16816(c[im][j], al, bh[j]);   // lo*hi
                }
            }
        }
        __syncthreads();
    }

    // Epilogue: c0,c1 -> (row, col..col+1); c2,c3 -> (row+8)
    #pragma unroll
    for (int im = 0; im < 2; im++) {
        int mr = row0 + wm * 32 + im * 16 + gq;
        #pragma unroll
        for (int j = 0; j < 8; j++) {
            int col = wn * 64 + j * 8 + gp * 2;
            if (mr < n)
                *(float2*)(C + (size_t)mr * DIM + col) = make_float2(c[im][j][0], c[im][j][1]);
            if (mr + 8 < n)
                *(float2*)(C + (size_t)(mr + 8) * DIM + col) = make_float2(c[im][j][2], c[im][j][3]);
        }
    }
}

// ---------------------------------------------------------------------------
// Fused aggregate: warp per node, dst-sorted CSR, unroll-4.
// out[d] = relu( h[d]*dinv[d]^2 + sum_e h[src_e]*norm_e + b )
// ---------------------------------------------------------------------------
__global__ __launch_bounds__(256) void aggregate_kernel(
    const float* __restrict__ h, const float* __restrict__ b,
    float* __restrict__ out)
{
    const int lane = threadIdx.x & 31;
    const int node = (blockIdx.x * blockDim.x + threadIdx.x) >> 5;
    if (node >= N_NODES) return;

    const int beg = g_off[node];
    const int end = g_off[node + 1];
    const float dv = g_dinv[node];
    const float sc = dv * dv;

    float4 acc = *(const float4*)(h + (size_t)node * DIM + lane * 4);
    acc.x *= sc; acc.y *= sc; acc.z *= sc; acc.w *= sc;

    int e = beg;
    for (; e + 4 <= end; e += 4) {
        int2 e0 = g_edge[e];
        int2 e1 = g_edge[e + 1];
        int2 e2 = g_edge[e + 2];
        int2 e3 = g_edge[e + 3];
        float4 v0 = *(const float4*)(h + (size_t)e0.x * DIM + lane * 4);
        float4 v1 = *(const float4*)(h + (size_t)e1.x * DIM + lane * 4);
        float4 v2 = *(const float4*)(h + (size_t)e2.x * DIM + lane * 4);
        float4 v3 = *(const float4*)(h + (size_t)e3.x * DIM + lane * 4);
        float n0 = __int_as_float(e0.y), n1 = __int_as_float(e1.y);
        float n2 = __int_as_float(e2.y), n3 = __int_as_float(e3.y);
        acc.x += v0.x * n0; acc.y += v0.y * n0; acc.z += v0.z * n0; acc.w += v0.w * n0;
        acc.x += v1.x * n1; acc.y += v1.y * n1; acc.z += v1.z * n1; acc.w += v1.w * n1;
        acc.x += v2.x * n2; acc.y += v2.y * n2; acc.z += v2.z * n2; acc.w += v2.w * n2;
        acc.x += v3.x * n3; acc.y += v3.y * n3; acc.z += v3.z * n3; acc.w += v3.w * n3;
    }
    for (; e < end; e++) {
        int2 e0 = g_edge[e];
        float n0 = __int_as_float(e0.y);
        float4 v0 = *(const float4*)(h + (size_t)e0.x * DIM + lane * 4);
        acc.x += v0.x * n0; acc.y += v0.y * n0; acc.z += v0.z * n0; acc.w += v0.w * n0;
    }

    float4 b4 = *(const float4*)(b + lane * 4);
    acc.x = fmaxf(acc.x + b4.x, 0.f);
    acc.y = fmaxf(acc.y + b4.y, 0.f);
    acc.z = fmaxf(acc.z + b4.z, 0.f);
    acc.w = fmaxf(acc.w + b4.w, 0.f);
    *(float4*)(out + (size_t)node * DIM + lane * 4) = acc;
}

// ---------------------------------------------------------------------------
// Launch
// ---------------------------------------------------------------------------
extern "C" void kernel_launch(void* const* d_in, const int* in_sizes, int n_in,
                              void* d_out, int out_size)
{
    const float* x   = (const float*)d_in[0];
    const int*   ei  = (const int*)  d_in[1];
    const float* W0  = (const float*)d_in[2];
    const float* b0  = (const float*)d_in[3];
    const float* W1  = (const float*)d_in[4];
    const float* b1  = (const float*)d_in[5];
    float*       out = (float*)d_out;

    const int* src = ei;
    const int* dst = ei + E_EDGES;

    float *h_ptr, *x1_ptr;
    __nv_bfloat16 *whi_ptr, *wlo_ptr;
    cudaGetSymbolAddress((void**)&h_ptr,   g_h);
    cudaGetSymbolAddress((void**)&x1_ptr,  g_x1);
    cudaGetSymbolAddress((void**)&whi_ptr, g_wt_hi);
    cudaGetSymbolAddress((void**)&wlo_ptr, g_wt_lo);

    const int TB = 256;
    const int gridN  = (N_NODES + TB - 1) / TB;
    const int gridE4 = (E_EDGES / 4 + TB - 1) / TB;
    const int gridG  = (N_NODES + GBM - 1) / GBM;
    const int gridA  = (N_NODES * 32 + TB - 1) / TB;
    const int gridW  = (DIM * DIM + TB - 1) / TB;

    // CSR + normalization + weight-split precompute
    zero_deg_kernel<<<gridN, TB>>>();
    hist_kernel<<<gridE4, TB>>>(dst);
    wsplit_kernel<<<gridW, TB>>>(W0, whi_ptr,            wlo_ptr);
    wsplit_kernel<<<gridW, TB>>>(W1, whi_ptr + DIM*DIM,  wlo_ptr + DIM*DIM);
    scan_kernel<<<1, 1024>>>();
    reorder_kernel<<<gridE4, TB>>>(src, dst);

    // layer 1
    gemm_tc_kernel<<<gridG, TB>>>(x, whi_ptr, wlo_ptr, h_ptr, N_NODES);
    aggregate_kernel<<<gridA, TB>>>(h_ptr, b0, x1_ptr);

    // layer 2
    gemm_tc_kernel<<<gridG, TB>>>(x1_ptr, whi_ptr + DIM*DIM, wlo_ptr + DIM*DIM, h_ptr, N_NODES);
    aggregate_kernel<<<gridA, TB>>>(h_ptr, b1, out);
}

// round 9
// speedup vs baseline: 1.8469x; 1.6130x over previous
#include <cuda_runtime.h>
#include <cuda_bf16.h>

#define N_NODES 50000
#define E_EDGES 1600000
#define DIM     128
#define SLOTS   96      // max degree bucket capacity (Poisson(32): P(>96) ~ 1e-20)

// ---------------------------------------------------------------------------
// Scratch (device globals — no allocation allowed)
// ---------------------------------------------------------------------------
__device__ float g_h   [N_NODES * DIM];       // h = x @ W
__device__ float g_x1  [N_NODES * DIM];       // layer-1 output
__device__ int   g_cnt [N_NODES];             // per-dst degree / insertion cursor
__device__ int2  g_pedge[N_NODES * SLOTS];    // padded: {src, __float_as_int(norm)}

// Pre-split weights, transposed to n-major: Wt[n][k], bf16 hi/lo
__device__ __nv_bfloat16 g_wt_hi[2][DIM * DIM];
__device__ __nv_bfloat16 g_wt_lo[2][DIM * DIM];

// ---------------------------------------------------------------------------
// Precompute: zero counts
// ---------------------------------------------------------------------------
__global__ void zero_cnt_kernel() {
    int i = blockIdx.x * blockDim.x + threadIdx.x;
    if (i < N_NODES) g_cnt[i] = 0;
}

// ---------------------------------------------------------------------------
// Bucket pass: count degree + drop src into its padded slot (ILP-4)
// ---------------------------------------------------------------------------
__global__ void bucket_kernel(const int* __restrict__ src, const int* __restrict__ dst) {
    int base = (blockIdx.x * blockDim.x + threadIdx.x) * 4;
    if (base < E_EDGES) {   // E divisible by 4
        int4 d4 = *(const int4*)(dst + base);
        int4 s4 = *(const int4*)(src + base);
        int p0 = atomicAdd(&g_cnt[d4.x], 1);
        int p1 = atomicAdd(&g_cnt[d4.y], 1);
        int p2 = atomicAdd(&g_cnt[d4.z], 1);
        int p3 = atomicAdd(&g_cnt[d4.w], 1);
        g_pedge[d4.x * SLOTS + p0].x = s4.x;
        g_pedge[d4.y * SLOTS + p1].x = s4.y;
        g_pedge[d4.z * SLOTS + p2].x = s4.z;
        g_pedge[d4.w * SLOTS + p3].x = s4.w;
    }
}

// ---------------------------------------------------------------------------
// Norm fill: warp per node. norm = rsqrt(cnt[d]+1) * rsqrt(cnt[s]+1)
// ---------------------------------------------------------------------------
__global__ __launch_bounds__(256) void normfill_kernel() {
    const int lane = threadIdx.x & 31;
    const int node = (blockIdx.x * blockDim.x + threadIdx.x) >> 5;   // 6250*8 = 50000
    if (node >= N_NODES) return;

    const int deg = g_cnt[node];
    const float dv = rsqrtf((float)(deg + 1));
    int2* ep = g_pedge + node * SLOTS;

    #pragma unroll
    for (int i = 0; i < 3; i++) {            // 3*32 = 96 slots
        int slot = lane + i * 32;
        if (slot < deg) {
            int s = ep[slot].x;
            float nm = dv * rsqrtf((float)(g_cnt[s] + 1));
            ep[slot] = make_int2(s, __float_as_int(nm));
        }
    }
}

// ---------------------------------------------------------------------------
// Weight prep: split BOTH W (k-major [k][n]) into bf16 hi/lo, transposed [n][k]
// ---------------------------------------------------------------------------
__global__ void wsplit_kernel(const float* __restrict__ W0, const float* __restrict__ W1) {
    int t = blockIdx.x * blockDim.x + threadIdx.x;   // 2 * 16384
    if (t < 2 * DIM * DIM) {
        int which = t >> 14;
        int idx   = t & (DIM * DIM - 1);
        int k = idx >> 7, n = idx & 127;
        float v = (which ? W1 : W0)[idx];
        __nv_bfloat16 h = __float2bfloat16(v);
        __nv_bfloat16 l = __float2bfloat16(v - __bfloat162float(h));
        g_wt_hi[which][n * DIM + k] = h;
        g_wt_lo[which][n * DIM + k] = l;
    }
}

// ---------------------------------------------------------------------------
// Tensor-core GEMM: C[n,128] = A[n,128] @ W[128,128] in split-bf16
// (unchanged from round 8 — hi*hi + hi*lo + lo*hi)
// ---------------------------------------------------------------------------
#define GBM  128
#define GBK  32
#define GPAD 40

__device__ __forceinline__ void mma16816(float* c, const unsigned* a, const unsigned* b) {
    asm volatile(
        "mma.sync.aligned.m16n8k16.row.col.f32.bf16.bf16.f32 "
        "{%0,%1,%2,%3}, {%4,%5,%6,%7}, {%8,%9}, {%0,%1,%2,%3};"
        : "+f"(c[0]), "+f"(c[1]), "+f"(c[2]), "+f"(c[3])
        : "r"(a[0]), "r"(a[1]), "r"(a[2]), "r"(a[3]), "r"(b[0]), "r"(b[1]));
}

__global__ __launch_bounds__(256) void gemm_tc_kernel(
    const float* __restrict__ A,
    const __nv_bfloat16* __restrict__ Wt_hi,
    const __nv_bfloat16* __restrict__ Wt_lo,
    float* __restrict__ C, int n)
{
    __shared__ __nv_bfloat16 sAh[GBM][GPAD];
    __shared__ __nv_bfloat16 sAl[GBM][GPAD];
    __shared__ __nv_bfloat16 sWh[DIM][GPAD];
    __shared__ __nv_bfloat16 sWl[DIM][GPAD];

    const int tid   = threadIdx.x;
    const int lane  = tid & 31;
    const int w     = tid >> 5;
    const int wm    = w & 3;
    const int wn    = w >> 2;
    const int gq    = lane >> 2;
    const int gp    = lane & 3;
    const int row0  = blockIdx.x * GBM;

    float c[2][8][4];
    #pragma unroll
    for (int im = 0; im < 2; im++)
        #pragma unroll
        for (int j = 0; j < 8; j++)
            #pragma unroll
            for (int q = 0; q < 4; q++) c[im][j][q] = 0.f;

    for (int kc = 0; kc < DIM; kc += GBK) {
        #pragma unroll
        for (int i = 0; i < 8; i++) {
            int idx = tid + i * 256;
            int m   = idx >> 4;
            int k2  = (idx & 15) * 2;
            int row = row0 + m;
            float2 v = (row < n) ? *(const float2*)(A + (size_t)row * DIM + kc + k2)
                                 : make_float2(0.f, 0.f);
            __nv_bfloat16 hx = __float2bfloat16(v.x);
            __nv_bfloat16 hy = __float2bfloat16(v.y);
            __nv_bfloat16 lx = __float2bfloat16(v.x - __bfloat162float(hx));
            __nv_bfloat16 ly = __float2bfloat16(v.y - __bfloat162float(hy));
            __nv_bfloat162 ph; ph.x = hx; ph.y = hy;
            __nv_bfloat162 pl; pl.x = lx; pl.y = ly;
            *(__nv_bfloat162*)&sAh[m][k2] = ph;
            *(__nv_bfloat162*)&sAl[m][k2] = pl;
        }
        #pragma unroll
        for (int i = 0; i < 8; i++) {
            int idx = tid + i * 256;
            int nn  = idx >> 4;
            int kp  = (idx & 15) * 2;
            *(unsigned*)&sWh[nn][kp] = *(const unsigned*)(Wt_hi + nn * DIM + kc + kp);
            *(unsigned*)&sWl[nn][kp] = *(const unsigned*)(Wt_lo + nn * DIM + kc + kp);
        }
        __syncthreads();

        #pragma unroll
        for (int ks = 0; ks < 2; ks++) {
            const int kb = ks * 16;
            unsigned bh[8][2], bl[8][2];
            #pragma unroll
            for (int j = 0; j < 8; j++) {
                int nn = wn * 64 + j * 8 + gq;
                bh[j][0] = *(const unsigned*)&sWh[nn][kb + gp * 2];
                bh[j][1] = *(const unsigned*)&sWh[nn][kb + gp * 2 + 8];
                bl[j][0] = *(const unsigned*)&sWl[nn][kb + gp * 2];
                bl[j][1] = *(const unsigned*)&sWl[nn][kb + gp * 2 + 8];
            }
            #pragma unroll
            for (int im = 0; im < 2; im++) {
                int mr = wm * 32 + im * 16 + gq;
                unsigned ah[4], al[4];
                ah[0] = *(const unsigned*)&sAh[mr    ][kb + gp * 2];
                ah[1] = *(const unsigned*)&sAh[mr + 8][kb + gp * 2];
                ah[2] = *(const unsigned*)&sAh[mr    ][kb + gp * 2 + 8];
                ah[3] = *(const unsigned*)&sAh[mr + 8][kb + gp * 2 + 8];
                al[0] = *(const unsigned*)&sAl[mr    ][kb + gp * 2];
                al[1] = *(const unsigned*)&sAl[mr + 8][kb + gp * 2];
                al[2] = *(const unsigned*)&sAl[mr    ][kb + gp * 2 + 8];
                al[3] = *(const unsigned*)&sAl[mr + 8][kb + gp * 2 + 8];
                #pragma unroll
                for (int j = 0; j < 8; j++) {
                    mma16816(c[im][j], ah, bh[j]);
                    mma16816(c[im][j], ah, bl[j]);
                    mma16816(c[im][j], al, bh[j]);
                }
            }
        }
        __syncthreads();
    }

    #pragma unroll
    for (int im = 0; im < 2; im++) {
        int mr = row0 + wm * 32 + im * 16 + gq;
        #pragma unroll
        for (int j = 0; j < 8; j++) {
            int col = wn * 64 + j * 8 + gp * 2;
            if (mr < n)
                *(float2*)(C + (size_t)mr * DIM + col) = make_float2(c[im][j][0], c[im][j][1]);
            if (mr + 8 < n)
                *(float2*)(C + (size_t)(mr + 8) * DIM + col) = make_float2(c[im][j][2], c[im][j][3]);
        }
    }
}

// ---------------------------------------------------------------------------
// Fused aggregate: warp per node, padded buckets, unroll-8 (MLP=8).
// out[d] = relu( h[d]*dinv[d]^2 + sum_e h[src_e]*norm_e + b )
// ---------------------------------------------------------------------------
__global__ __launch_bounds__(256) void aggregate_kernel(
    const float* __restrict__ h, const float* __restrict__ b,
    float* __restrict__ out)
{
    const int lane = threadIdx.x & 31;
    const int node = (blockIdx.x * blockDim.x + threadIdx.x) >> 5;
    if (node >= N_NODES) return;

    const int deg = g_cnt[node];
    const float dv = rsqrtf((float)(deg + 1));
    const float sc = dv * dv;
    const int2* ep = g_pedge + node * SLOTS;

    float4 acc = *(const float4*)(h + (size_t)node * DIM + lane * 4);
    acc.x *= sc; acc.y *= sc; acc.z *= sc; acc.w *= sc;

    int e = 0;
    for (; e + 8 <= deg; e += 8) {
        int2 ed[8];
        #pragma unroll
        for (int i = 0; i < 8; i++) ed[i] = ep[e + i];
        float4 v[8];
        #pragma unroll
        for (int i = 0; i < 8; i++)
            v[i] = *(const float4*)(h + (size_t)ed[i].x * DIM + lane * 4);
        #pragma unroll
        for (int i = 0; i < 8; i++) {
            float nm = __int_as_float(ed[i].y);
            acc.x += v[i].x * nm; acc.y += v[i].y * nm;
            acc.z += v[i].z * nm; acc.w += v[i].w * nm;
        }
    }
    for (; e + 2 <= deg; e += 2) {
        int2 e0 = ep[e], e1 = ep[e + 1];
        float4 v0 = *(const float4*)(h + (size_t)e0.x * DIM + lane * 4);
        float4 v1 = *(const float4*)(h + (size_t)e1.x * DIM + lane * 4);
        float n0 = __int_as_float(e0.y), n1 = __int_as_float(e1.y);
        acc.x += v0.x * n0; acc.y += v0.y * n0; acc.z += v0.z * n0; acc.w += v0.w * n0;
        acc.x += v1.x * n1; acc.y += v1.y * n1; acc.z += v1.z * n1; acc.w += v1.w * n1;
    }
    if (e < deg) {
        int2 e0 = ep[e];
        float n0 = __int_as_float(e0.y);
        float4 v0 = *(const float4*)(h + (size_t)e0.x * DIM + lane * 4);
        acc.x += v0.x * n0; acc.y += v0.y * n0; acc.z += v0.z * n0; acc.w += v0.w * n0;
    }

    float4 b4 = *(const float4*)(b + lane * 4);
    acc.x = fmaxf(acc.x + b4.x, 0.f);
    acc.y = fmaxf(acc.y + b4.y, 0.f);
    acc.z = fmaxf(acc.z + b4.z, 0.f);
    acc.w = fmaxf(acc.w + b4.w, 0.f);
    *(float4*)(out + (size_t)node * DIM + lane * 4) = acc;
}

// ---------------------------------------------------------------------------
// Launch: fork-join two streams so CSR build overlaps {wsplit, GEMM1}
// ---------------------------------------------------------------------------
extern "C" void kernel_launch(void* const* d_in, const int* in_sizes, int n_in,
                              void* d_out, int out_size)
{
    const float* x   = (const float*)d_in[0];
    const int*   ei  = (const int*)  d_in[1];
    const float* W0  = (const float*)d_in[2];
    const float* b0  = (const float*)d_in[3];
    const float* W1  = (const float*)d_in[4];
    const float* b1  = (const float*)d_in[5];
    float*       out = (float*)d_out;

    const int* src = ei;
    const int* dst = ei + E_EDGES;

    float *h_ptr, *x1_ptr;
    __nv_bfloat16 *whi_ptr, *wlo_ptr;
    cudaGetSymbolAddress((void**)&h_ptr,   g_h);
    cudaGetSymbolAddress((void**)&x1_ptr,  g_x1);
    cudaGetSymbolAddress((void**)&whi_ptr, g_wt_hi);
    cudaGetSymbolAddress((void**)&wlo_ptr, g_wt_lo);

    const int TB = 256;
    const int gridN  = (N_NODES + TB - 1) / TB;
    const int gridE4 = (E_EDGES / 4 + TB - 1) / TB;
    const int gridG  = (N_NODES + GBM - 1) / GBM;
    const int gridA  = (N_NODES * 32 + TB - 1) / TB;
    const int gridW  = (2 * DIM * DIM + TB - 1) / TB;

    // Fork a second stream (created fresh each call; kernel_launch is invoked
    // only for the correctness run and the single capture — no resource growth).
    cudaStream_t s2;
    cudaStreamCreate(&s2);
    cudaEvent_t evF, evJ;
    cudaEventCreateWithFlags(&evF, cudaEventDisableTiming);
    cudaEventCreateWithFlags(&evJ, cudaEventDisableTiming);

    cudaEventRecord(evF, 0);
    cudaStreamWaitEvent(s2, evF, 0);

    // Stream 0: graph/CSR chain
    zero_cnt_kernel<<<gridN, TB>>>();
    bucket_kernel<<<gridE4, TB>>>(src, dst);
    normfill_kernel<<<gridA, TB>>>();

    // Stream s2: weight split + layer-1 GEMM (independent of the graph chain)
    wsplit_kernel<<<gridW, TB, 0, s2>>>(W0, W1);
    gemm_tc_kernel<<<gridG, TB, 0, s2>>>(x, whi_ptr, wlo_ptr, h_ptr, N_NODES);

    cudaEventRecord(evJ, s2);
    cudaStreamWaitEvent(0, evJ, 0);

    // Stream 0: rest of the pipeline (serial dependencies)
    aggregate_kernel<<<gridA, TB>>>(h_ptr, b0, x1_ptr);
    gemm_tc_kernel<<<gridG, TB>>>(x1_ptr, whi_ptr + DIM * DIM, wlo_ptr + DIM * DIM,
                                  h_ptr, N_NODES);
    aggregate_kernel<<<gridA, TB>>>(h_ptr, b1, out);
}

// round 10
// speedup vs baseline: 1.9640x; 1.0634x over previous
#include <cuda_runtime.h>
#include <cuda_bf16.h>
#include <cuda_fp16.h>

#define N_NODES 50000
#define NODE_HALF 25000
#define E_EDGES 1600000
#define DIM     128
#define SLOTS   96      // max degree bucket capacity (Poisson(32): P(>96) ~ 1e-20)

// ---------------------------------------------------------------------------
// Scratch (device globals — no allocation allowed)
// ---------------------------------------------------------------------------
__device__ float  g_h   [N_NODES * DIM];      // h = x @ W   (fp32, self-term + next input)
__device__ __half g_hf  [N_NODES * DIM];      // fp16 copy for gathers
__device__ float  g_x1  [N_NODES * DIM];      // layer-1 output
__device__ int    g_cnt [N_NODES];            // per-dst degree / insertion cursor
__device__ float  g_dinvf[N_NODES];           // rsqrt(deg+1)
__device__ int    g_psrc[N_NODES * SLOTS];    // padded bucket: src ids

// Pre-split weights, transposed to n-major: Wt[n][k], bf16 hi/lo
__device__ __nv_bfloat16 g_wt_hi[2][DIM * DIM];
__device__ __nv_bfloat16 g_wt_lo[2][DIM * DIM];

// ---------------------------------------------------------------------------
// Precompute
// ---------------------------------------------------------------------------
__global__ void zero_cnt_kernel() {
    int i = blockIdx.x * blockDim.x + threadIdx.x;
    if (i < N_NODES) g_cnt[i] = 0;
}

__global__ void bucket_kernel(const int* __restrict__ src, const int* __restrict__ dst) {
    int base = (blockIdx.x * blockDim.x + threadIdx.x) * 4;
    if (base < E_EDGES) {   // E divisible by 4
        int4 d4 = *(const int4*)(dst + base);
        int4 s4 = *(const int4*)(src + base);
        int p0 = atomicAdd(&g_cnt[d4.x], 1);
        int p1 = atomicAdd(&g_cnt[d4.y], 1);
        int p2 = atomicAdd(&g_cnt[d4.z], 1);
        int p3 = atomicAdd(&g_cnt[d4.w], 1);
        g_psrc[d4.x * SLOTS + p0] = s4.x;
        g_psrc[d4.y * SLOTS + p1] = s4.y;
        g_psrc[d4.z * SLOTS + p2] = s4.z;
        g_psrc[d4.w * SLOTS + p3] = s4.w;
    }
}

__global__ void dinv_kernel() {
    int i = blockIdx.x * blockDim.x + threadIdx.x;
    if (i < N_NODES) g_dinvf[i] = rsqrtf((float)(g_cnt[i] + 1));
}

// ---------------------------------------------------------------------------
// Weight prep: split BOTH W (k-major [k][n]) into bf16 hi/lo, transposed [n][k]
// ---------------------------------------------------------------------------
__global__ void wsplit_kernel(const float* __restrict__ W0, const float* __restrict__ W1) {
    int t = blockIdx.x * blockDim.x + threadIdx.x;   // 2 * 16384
    if (t < 2 * DIM * DIM) {
        int which = t >> 14;
        int idx   = t & (DIM * DIM - 1);
        int k = idx >> 7, n = idx & 127;
        float v = (which ? W1 : W0)[idx];
        __nv_bfloat16 h = __float2bfloat16(v);
        __nv_bfloat16 l = __float2bfloat16(v - __bfloat162float(h));
        g_wt_hi[which][n * DIM + k] = h;
        g_wt_lo[which][n * DIM + k] = l;
    }
}

// ---------------------------------------------------------------------------
// Tensor-core GEMM: C[n,128] = A[n,128] @ W[128,128] in split-bf16
// Dual epilogue: fp32 C + fp16 Cf (gather copy).
// ---------------------------------------------------------------------------
#define GBM  128
#define GBK  32
#define GPAD 40

__device__ __forceinline__ void mma16816(float* c, const unsigned* a, const unsigned* b) {
    asm volatile(
        "mma.sync.aligned.m16n8k16.row.col.f32.bf16.bf16.f32 "
        "{%0,%1,%2,%3}, {%4,%5,%6,%7}, {%8,%9}, {%0,%1,%2,%3};"
        : "+f"(c[0]), "+f"(c[1]), "+f"(c[2]), "+f"(c[3])
        : "r"(a[0]), "r"(a[1]), "r"(a[2]), "r"(a[3]), "r"(b[0]), "r"(b[1]));
}

__global__ __launch_bounds__(256) void gemm_tc_kernel(
    const float* __restrict__ A,
    const __nv_bfloat16* __restrict__ Wt_hi,
    const __nv_bfloat16* __restrict__ Wt_lo,
    float* __restrict__ C, __half* __restrict__ Cf, int n)
{
    __shared__ __nv_bfloat16 sAh[GBM][GPAD];
    __shared__ __nv_bfloat16 sAl[GBM][GPAD];
    __shared__ __nv_bfloat16 sWh[DIM][GPAD];
    __shared__ __nv_bfloat16 sWl[DIM][GPAD];

    const int tid   = threadIdx.x;
    const int lane  = tid & 31;
    const int w     = tid >> 5;
    const int wm    = w & 3;
    const int wn    = w >> 2;
    const int gq    = lane >> 2;
    const int gp    = lane & 3;
    const int row0  = blockIdx.x * GBM;

    float c[2][8][4];
    #pragma unroll
    for (int im = 0; im < 2; im++)
        #pragma unroll
        for (int j = 0; j < 8; j++)
            #pragma unroll
            for (int q = 0; q < 4; q++) c[im][j][q] = 0.f;

    for (int kc = 0; kc < DIM; kc += GBK) {
        #pragma unroll
        for (int i = 0; i < 8; i++) {
            int idx = tid + i * 256;
            int m   = idx >> 4;
            int k2  = (idx & 15) * 2;
            int row = row0 + m;
            float2 v = (row < n) ? *(const float2*)(A + (size_t)row * DIM + kc + k2)
                                 : make_float2(0.f, 0.f);
            __nv_bfloat16 hx = __float2bfloat16(v.x);
            __nv_bfloat16 hy = __float2bfloat16(v.y);
            __nv_bfloat16 lx = __float2bfloat16(v.x - __bfloat162float(hx));
            __nv_bfloat16 ly = __float2bfloat16(v.y - __bfloat162float(hy));
            __nv_bfloat162 ph; ph.x = hx; ph.y = hy;
            __nv_bfloat162 pl; pl.x = lx; pl.y = ly;
            *(__nv_bfloat162*)&sAh[m][k2] = ph;
            *(__nv_bfloat162*)&sAl[m][k2] = pl;
        }
        #pragma unroll
        for (int i = 0; i < 8; i++) {
            int idx = tid + i * 256;
            int nn  = idx >> 4;
            int kp  = (idx & 15) * 2;
            *(unsigned*)&sWh[nn][kp] = *(const unsigned*)(Wt_hi + nn * DIM + kc + kp);
            *(unsigned*)&sWl[nn][kp] = *(const unsigned*)(Wt_lo + nn * DIM + kc + kp);
        }
        __syncthreads();

        #pragma unroll
        for (int ks = 0; ks < 2; ks++) {
            const int kb = ks * 16;
            unsigned bh[8][2], bl[8][2];
            #pragma unroll
            for (int j = 0; j < 8; j++) {
                int nn = wn * 64 + j * 8 + gq;
                bh[j][0] = *(const unsigned*)&sWh[nn][kb + gp * 2];
                bh[j][1] = *(const unsigned*)&sWh[nn][kb + gp * 2 + 8];
                bl[j][0] = *(const unsigned*)&sWl[nn][kb + gp * 2];
                bl[j][1] = *(const unsigned*)&sWl[nn][kb + gp * 2 + 8];
            }
            #pragma unroll
            for (int im = 0; im < 2; im++) {
                int mr = wm * 32 + im * 16 + gq;
                unsigned ah[4], al[4];
                ah[0] = *(const unsigned*)&sAh[mr    ][kb + gp * 2];
                ah[1] = *(const unsigned*)&sAh[mr + 8][kb + gp * 2];
                ah[2] = *(const unsigned*)&sAh[mr    ][kb + gp * 2 + 8];
                ah[3] = *(const unsigned*)&sAh[mr + 8][kb + gp * 2 + 8];
                al[0] = *(const unsigned*)&sAl[mr    ][kb + gp * 2];
                al[1] = *(const unsigned*)&sAl[mr + 8][kb + gp * 2];
                al[2] = *(const unsigned*)&sAl[mr    ][kb + gp * 2 + 8];
                al[3] = *(const unsigned*)&sAl[mr + 8][kb + gp * 2 + 8];
                #pragma unroll
                for (int j = 0; j < 8; j++) {
                    mma16816(c[im][j], ah, bh[j]);
                    mma16816(c[im][j], ah, bl[j]);
                    mma16816(c[im][j], al, bh[j]);
                }
            }
        }
        __syncthreads();
    }

    #pragma unroll
    for (int im = 0; im < 2; im++) {
        int mr = row0 + wm * 32 + im * 16 + gq;
        #pragma unroll
        for (int j = 0; j < 8; j++) {
            int col = wn * 64 + j * 8 + gp * 2;
            if (mr < n) {
                *(float2*)(C + (size_t)mr * DIM + col) = make_float2(c[im][j][0], c[im][j][1]);
                *(__half2*)(Cf + (size_t)mr * DIM + col) = __floats2half2_rn(c[im][j][0], c[im][j][1]);
            }
            if (mr + 8 < n) {
                *(float2*)(C + (size_t)(mr + 8) * DIM + col) = make_float2(c[im][j][2], c[im][j][3]);
                *(__half2*)(Cf + (size_t)(mr + 8) * DIM + col) = __floats2half2_rn(c[im][j][2], c[im][j][3]);
            }
        }
    }
}

// ---------------------------------------------------------------------------
// Fused aggregate: warp per node, padded buckets, fp16 gathers, unroll-8.
// out[d] = relu( h[d]*dinv[d]^2 + sum_e hf[src_e]*dinv[d]*dinv[src_e] + b )
// ---------------------------------------------------------------------------
__global__ __launch_bounds__(256) void aggregate_kernel(
    const float* __restrict__ h, const __half* __restrict__ hf,
    const float* __restrict__ b, float* __restrict__ out, int node_base)
{
    const int lane = threadIdx.x & 31;
    const int node = node_base + ((blockIdx.x * blockDim.x + threadIdx.x) >> 5);
    if (node >= N_NODES) return;

    const int deg  = g_cnt[node];
    const float dv = g_dinvf[node];
    const float sc = dv * dv;
    const int* sp  = g_psrc + node * SLOTS;

    float4 acc = *(const float4*)(h + (size_t)node * DIM + lane * 4);
    acc.x *= sc; acc.y *= sc; acc.z *= sc; acc.w *= sc;

    int e = 0;
    for (; e + 8 <= deg; e += 8) {
        int s[8];
        #pragma unroll
        for (int i = 0; i < 8; i++) s[i] = sp[e + i];
        uint2 raw[8];
        float nm[8];
        #pragma unroll
        for (int i = 0; i < 8; i++) {
            raw[i] = *(const uint2*)(hf + (size_t)s[i] * DIM + lane * 4);
            nm[i]  = dv * g_dinvf[s[i]];
        }
        #pragma unroll
        for (int i = 0; i < 8; i++) {
            float2 f0 = __half22float2(*(__half2*)&raw[i].x);
            float2 f1 = __half22float2(*(__half2*)&raw[i].y);
            acc.x += f0.x * nm[i]; acc.y += f0.y * nm[i];
            acc.z += f1.x * nm[i]; acc.w += f1.y * nm[i];
        }
    }
    for (; e < deg; e++) {
        int s = sp[e];
        float nm = dv * g_dinvf[s];
        uint2 raw = *(const uint2*)(hf + (size_t)s * DIM + lane * 4);
        float2 f0 = __half22float2(*(__half2*)&raw.x);
        float2 f1 = __half22float2(*(__half2*)&raw.y);
        acc.x += f0.x * nm; acc.y += f0.y * nm;
        acc.z += f1.x * nm; acc.w += f1.y * nm;
    }

    float4 b4 = *(const float4*)(b + lane * 4);
    acc.x = fmaxf(acc.x + b4.x, 0.f);
    acc.y = fmaxf(acc.y + b4.y, 0.f);
    acc.z = fmaxf(acc.z + b4.z, 0.f);
    acc.w = fmaxf(acc.w + b4.w, 0.f);
    *(float4*)(out + (size_t)node * DIM + lane * 4) = acc;
}

// ---------------------------------------------------------------------------
// Launch: two-stream fork-join with chunk-pipelined agg1/gemm2
// ---------------------------------------------------------------------------
extern "C" void kernel_launch(void* const* d_in, const int* in_sizes, int n_in,
                              void* d_out, int out_size)
{
    const float* x   = (const float*)d_in[0];
    const int*   ei  = (const int*)  d_in[1];
    const float* W0  = (const float*)d_in[2];
    const float* b0  = (const float*)d_in[3];
    const float* W1  = (const float*)d_in[4];
    const float* b1  = (const float*)d_in[5];
    float*       out = (float*)d_out;

    const int* src = ei;
    const int* dst = ei + E_EDGES;

    float *h_ptr, *x1_ptr;
    __half *hf_ptr;
    __nv_bfloat16 *whi_ptr, *wlo_ptr;
    cudaGetSymbolAddress((void**)&h_ptr,   g_h);
    cudaGetSymbolAddress((void**)&hf_ptr,  g_hf);
    cudaGetSymbolAddress((void**)&x1_ptr,  g_x1);
    cudaGetSymbolAddress((void**)&whi_ptr, g_wt_hi);
    cudaGetSymbolAddress((void**)&wlo_ptr, g_wt_lo);

    const int TB = 256;
    const int gridN   = (N_NODES + TB - 1) / TB;
    const int gridE4  = (E_EDGES / 4 + TB - 1) / TB;
    const int gridG   = (N_NODES + GBM - 1) / GBM;
    const int gridGh  = (NODE_HALF + GBM - 1) / GBM;
    const int gridA   = (N_NODES * 32 + TB - 1) / TB;
    const int gridAh  = (NODE_HALF * 32 + TB - 1) / TB;
    const int gridW   = (2 * DIM * DIM + TB - 1) / TB;

    cudaStream_t s2;
    cudaStreamCreate(&s2);
    cudaEvent_t evF, evP, evG1, evC1;
    cudaEventCreateWithFlags(&evF,  cudaEventDisableTiming);
    cudaEventCreateWithFlags(&evP,  cudaEventDisableTiming);
    cudaEventCreateWithFlags(&evG1, cudaEventDisableTiming);
    cudaEventCreateWithFlags(&evC1, cudaEventDisableTiming);

    cudaEventRecord(evF, 0);
    cudaStreamWaitEvent(s2, evF, 0);

    // Stream 0: graph precompute
    zero_cnt_kernel<<<gridN, TB>>>();
    bucket_kernel<<<gridE4, TB>>>(src, dst);
    dinv_kernel<<<gridN, TB>>>();
    cudaEventRecord(evP, 0);

    // Stream s2: weight split + full layer-1 GEMM
    wsplit_kernel<<<gridW, TB, 0, s2>>>(W0, W1);
    gemm_tc_kernel<<<gridG, TB, 0, s2>>>(x, whi_ptr, wlo_ptr, h_ptr, hf_ptr, N_NODES);
    cudaEventRecord(evG1, s2);

    // Stream 0: agg1 chunk0 -> gemm2 chunk0   (needs precompute + gemm1)
    cudaStreamWaitEvent(0, evG1, 0);
    aggregate_kernel<<<gridAh, TB>>>(h_ptr, hf_ptr, b0, x1_ptr, 0);
    gemm_tc_kernel<<<gridGh, TB>>>(x1_ptr, whi_ptr + DIM * DIM, wlo_ptr + DIM * DIM,
                                   h_ptr, hf_ptr, NODE_HALF);

    // Stream s2: agg1 chunk1 -> gemm2 chunk1  (needs precompute, has gemm1)
    cudaStreamWaitEvent(s2, evP, 0);
    aggregate_kernel<<<gridAh, TB, 0, s2>>>(h_ptr, hf_ptr, b0, x1_ptr, NODE_HALF);
    gemm_tc_kernel<<<gridGh, TB, 0, s2>>>(
        x1_ptr + (size_t)NODE_HALF * DIM,
        whi_ptr + DIM * DIM, wlo_ptr + DIM * DIM,
        h_ptr + (size_t)NODE_HALF * DIM, hf_ptr + (size_t)NODE_HALF * DIM, NODE_HALF);
    cudaEventRecord(evC1, s2);

    // Stream 0: final aggregate (needs both gemm2 chunks)
    cudaStreamWaitEvent(0, evC1, 0);
    aggregate_kernel<<<gridA, TB>>>(h_ptr, hf_ptr, b1, out, 0);
}